// round 11
// baseline (speedup 1.0000x reference)
#include <cuda_runtime.h>
#include <cuda_bf16.h>
#include <stdint.h>
#include <math.h>

// ---------------- problem constants ----------------
#define GSIZE   8
#define IDIM    1024
#define ODIM    1024
#define BATCH   4096
#define NF      19                  // 8 cos + 8 sin + 3 base-split features
#define KDIM    (NF * IDIM)         // 19456

// ---------------- GEMM tiling ----------------
#define BM      128
#define BN      128
#define BK      64                  // K per pipeline stage (128B rows)
#define NKC     (KDIM / BK)         // 304
#define STAGES  3
#define NTH     128                 // 4 warps: 2 (m) x 2 (n), warp tile 64x64

#define A_TILE_BYTES (BM * BK * 2)            // 16384
#define B_TILE_BYTES (BN * BK * 2)            // 16384
#define STAGE_BYTES  (A_TILE_BYTES + B_TILE_BYTES) // 32768
#define SMEM_BYTES   (1024 + STAGES * STAGE_BYTES + 256) // tiles + mbarriers

#define ROWB         (KDIM * 2)     // gmem row stride in bytes (38912, 16B-aligned)

// ---------------- scratch (no allocs allowed) ----------------
__device__ __align__(1024) __nv_bfloat16 g_A[(size_t)BATCH * KDIM]; // ~152 MB
__device__ __align__(1024) __nv_bfloat16 g_W[(size_t)ODIM  * KDIM]; // ~40 MB

// ---------------- PTX helpers (base-arch only: sm_80/90 non-"a") ----------------
__device__ __forceinline__ uint32_t smem_u32(const void* p) {
    uint32_t a;
    asm("{ .reg .u64 t; cvta.to.shared.u64 t, %1; cvt.u32.u64 %0, t; }" : "=r"(a) : "l"(p));
    return a;
}

__device__ __forceinline__ void cp16(uint32_t s, const void* g) {
    asm volatile("cp.async.cg.shared.global [%0], [%1], 16;" :: "r"(s), "l"(g) : "memory");
}

#define MBAR_INIT(a, c) \
    asm volatile("mbarrier.init.shared.b64 [%0], %1;" :: "r"(a), "r"(c) : "memory")
#define MBAR_ARRIVE(a) \
    asm volatile("mbarrier.arrive.shared.b64 _, [%0];" :: "r"(a) : "memory")
#define CP_MBAR_ARRIVE(a) \
    asm volatile("cp.async.mbarrier.arrive.noinc.shared.b64 [%0];" :: "r"(a) : "memory")

__device__ __forceinline__ void mbar_wait(uint32_t addr, uint32_t parity) {
    asm volatile(
        "{\n\t.reg .pred P;\n\t"
        "WL%=:\n\t"
        "mbarrier.try_wait.parity.acquire.cta.shared::cta.b64 P, [%0], %1, 0x989680;\n\t"
        "@P bra.uni WD%=;\n\t"
        "bra.uni WL%=;\n\t"
        "WD%=:\n\t}"
        :: "r"(addr), "r"(parity) : "memory");
}

__device__ __forceinline__ void ldsm_x4(uint32_t* r, uint32_t addr) {
    asm volatile("ldmatrix.sync.aligned.m8n8.x4.shared.b16 {%0,%1,%2,%3}, [%4];"
                 : "=r"(r[0]), "=r"(r[1]), "=r"(r[2]), "=r"(r[3]) : "r"(addr));
}

__device__ __forceinline__ void mma16816(float* d, const uint32_t* a, uint32_t b0, uint32_t b1) {
    asm volatile("mma.sync.aligned.m16n8k16.row.col.f32.bf16.bf16.f32 "
                 "{%0,%1,%2,%3}, {%4,%5,%6,%7}, {%8,%9}, {%0,%1,%2,%3};"
                 : "+f"(d[0]), "+f"(d[1]), "+f"(d[2]), "+f"(d[3])
                 : "r"(a[0]), "r"(a[1]), "r"(a[2]), "r"(a[3]), "r"(b0), "r"(b1));
}

// ---------------- kernel 1: feature matrix F[b, k] ----------------
// k = t*IDIM + i; t: 0..7 cos((t+1)x), 8..15 sin((t-7)x), 16 silu_hi, 17 silu_lo, 18 silu_hi
__global__ void __launch_bounds__(256) kan_features(const float* __restrict__ x) {
    int idx = blockIdx.x * blockDim.x + threadIdx.x;     // b*IDIM + i
    if (idx >= BATCH * IDIM) return;
    int b = idx >> 10, i = idx & (IDIM - 1);
    float v = x[idx];

    float s1, c1;
    __sincosf(v, &s1, &c1);     // |err| ~1e-6 over N(0,1) range; bf16 eps dominates
    __nv_bfloat16* dst = g_A + (size_t)b * KDIM + i;

    float ck = c1, sk = s1;
    dst[0 * IDIM] = __float2bfloat16_rn(ck);
    dst[8 * IDIM] = __float2bfloat16_rn(sk);
#pragma unroll
    for (int g = 1; g < GSIZE; g++) {
        float cn = ck * c1 - sk * s1;   // exact angle-addition recurrence
        float sn = sk * c1 + ck * s1;
        ck = cn; sk = sn;
        dst[g * IDIM]       = __float2bfloat16_rn(ck);
        dst[(8 + g) * IDIM] = __float2bfloat16_rn(sk);
    }

    float sig = 1.0f / (1.0f + __expf(-v));
    float su  = v * sig;                             // silu(x)
    __nv_bfloat16 hi = __float2bfloat16_rn(su);
    float lo = su - __bfloat162float(hi);
    dst[16 * IDIM] = hi;
    dst[17 * IDIM] = __float2bfloat16_rn(lo);
    dst[18 * IDIM] = hi;
}

// ---------------- kernel 2: packed weights W[o, k] ----------------
__global__ void __launch_bounds__(256) kan_pack(const float* __restrict__ scale_base,
                                                const float* __restrict__ scale_spline,
                                                const float* __restrict__ coeff) {
    int idx = blockIdx.x * blockDim.x + threadIdx.x;     // o*IDIM + i
    if (idx >= ODIM * IDIM) return;
    int o = idx >> 10, i = idx & (IDIM - 1);

    float ss = scale_spline[idx];
    __nv_bfloat16* dst = g_W + (size_t)o * KDIM + i;
    const float* c0 = coeff + ((size_t)o * IDIM + i) * GSIZE;
    const float* c1 = coeff + (size_t)ODIM * IDIM * GSIZE + ((size_t)o * IDIM + i) * GSIZE;

#pragma unroll
    for (int g = 0; g < GSIZE; g++) {
        dst[g * IDIM]       = __float2bfloat16_rn(ss * c0[g]);   // pairs with cos
        dst[(8 + g) * IDIM] = __float2bfloat16_rn(ss * c1[g]);   // pairs with sin
    }
    float sb = scale_base[idx];
    __nv_bfloat16 bh = __float2bfloat16_rn(sb);
    float bl = sb - __bfloat162float(bh);
    dst[16 * IDIM] = bh;                         // pairs with silu_hi
    dst[17 * IDIM] = bh;                         // pairs with silu_lo
    dst[18 * IDIM] = __float2bfloat16_rn(bl);    // pairs with silu_hi
}

// ---------------- kernel 3: pipelined HMMA GEMM out = F @ W^T ----------------
// 256 CTAs, 2/SM, 128 threads (4 warps of 64x64), 3-stage mbarrier pipeline.
// full[s]: count 128, arrived by per-thread cp.async.mbarrier.arrive.noinc.
// empty[s]: count 4, arrived by lane 0 of each warp after its last ldsm of a chunk.
// No __syncthreads / wait_group in the mainloop: warps flow independently.

__global__ void __launch_bounds__(NTH, 2)
kan_gemm(float* __restrict__ out) {
    extern __shared__ char smem_raw[];
    uint32_t sbase = (smem_u32(smem_raw) + 1023u) & ~1023u;
    uint32_t mb    = sbase + STAGES * STAGE_BYTES;      // full[s]=mb+16s, empty[s]=mb+16s+8

    int tid  = threadIdx.x;
    int lane = tid & 31, wid = tid >> 5;
    int wm = wid & 1, wn = wid >> 1;           // 2 x 2 warp grid, warp tile 64x64
    int mt  = blockIdx.x & 31;                 // 32 m-tiles
    int ntb = blockIdx.x >> 5;                 // 8 n-tiles
    int off = (blockIdx.x >= 148) ? (NKC / 2) : 0;   // stagger co-resident CTAs

    const char* gA0 = (const char*)(g_A + (size_t)(mt * BM) * KDIM);
    const char* gB0 = (const char*)(g_W + (size_t)(ntb * BN) * KDIM);

    if (tid == 0) {
#pragma unroll
        for (int s = 0; s < STAGES; s++) {
            MBAR_INIT(mb + s * 16,     128);   // full
            MBAR_INIT(mb + s * 16 + 8, 4);     // empty
        }
    }
    __syncthreads();

    // per-thread stage-load addressing (row0 = tid/8 in 0..15, +16 per sub-load)
    int r0   = tid >> 3;
    int colb = (tid & 7) * 16;
    uint32_t swc    = (uint32_t)(colb ^ ((r0 & 7) * 16));   // swizzle invariant in t
    uint32_t sA_off = (uint32_t)r0 * 128 + swc;
    size_t   g_off  = (size_t)r0 * ROWB + colb;

    // ---- prologue: fill STAGES-1 stages ----
#pragma unroll
    for (int s = 0; s < STAGES - 1; s++) {
        int c = s + off; if (c >= NKC) c -= NKC;
        uint32_t st = sbase + s * STAGE_BYTES;
        const char* ga = gA0 + (size_t)c * 128 + g_off;
        const char* gb = gB0 + (size_t)c * 128 + g_off;
#pragma unroll
        for (int t = 0; t < 8; t++) {
            cp16(st + sA_off + t * 2048,                ga + (size_t)t * (16 * ROWB));
            cp16(st + A_TILE_BYTES + sA_off + t * 2048, gb + (size_t)t * (16 * ROWB));
        }
        CP_MBAR_ARRIVE(mb + s * 16);
    }

    float acc[4][8][4];                        // [m16 tile][n8 tile][frag] = 128 regs
#pragma unroll
    for (int a = 0; a < 4; a++)
#pragma unroll
        for (int b = 0; b < 8; b++)
#pragma unroll
            for (int c = 0; c < 4; c++) acc[a][b][c] = 0.f;

    // per-lane ldmatrix address components
    int laA = lane & 15;                       // A row offset within m16
    int lcA = (lane >> 4) * 16;                // A col byte offset (k8 half)
    int bjj = lane >> 3;                       // B quad index
    int laB = ((bjj >> 1) << 3) + (lane & 7);  // B row offset within n16
    int lcB = (bjj & 1) * 16;                  // B col byte offset

    int fc_s = 0,          fc_p = 0;           // consumer cursor on full[]
    int ec_s = STAGES - 1, ec_p = 1;           // producer cursor on empty[]
    for (int kc = 0; kc < NKC; kc++) {
        mbar_wait(mb + fc_s * 16, (uint32_t)fc_p);

        int  lkc    = kc + STAGES - 1;
        bool doload = lkc < NKC;
        int  lck    = lkc + off; if (lck >= NKC) lck -= NKC;
        uint32_t ldst = sbase + ec_s * STAGE_BYTES;
        const char* lga = gA0 + (size_t)lck * 128 + g_off;
        const char* lgb = gB0 + (size_t)lck * 128 + g_off;

        uint32_t sA = sbase + fc_s * STAGE_BYTES;
        uint32_t sB = sA + A_TILE_BYTES;

#pragma unroll
        for (int ks = 0; ks < 4; ks++) {       // 4 x k16 per stage
            uint32_t af[4][4];
#pragma unroll
            for (int m2 = 0; m2 < 4; m2++) {
                int row = wm * 64 + m2 * 16 + laA;
                uint32_t addr = sA + row * 128 + ((ks * 32 + lcA) ^ ((row & 7) * 16));
                ldsm_x4(af[m2], addr);
            }
            uint32_t bf[4][4];
#pragma unroll
            for (int n2 = 0; n2 < 4; n2++) {
                int row = wn * 64 + n2 * 16 + laB;
                uint32_t addr = sB + row * 128 + ((ks * 32 + lcB) ^ ((row & 7) * 16));
                ldsm_x4(bf[n2], addr);         // r0,r1: n0-7 (k0,k8); r2,r3: n8-15
            }
            if (ks == 3 && lane == 0)          // all this warp's reads of stage fc_s issued
                MBAR_ARRIVE(mb + fc_s * 16 + 8);
            if (doload) {
                if (ks == 0)                   // gate stores on stage reuse, off hot path
                    mbar_wait(mb + ec_s * 16 + 8, (uint32_t)ec_p);
#pragma unroll
                for (int u = 0; u < 2; u++) {  // spread 16 cp16 across the 4 ks groups
                    int t = ks * 2 + u;
                    cp16(ldst + sA_off + t * 2048,
                         lga + (size_t)t * (16 * ROWB));
                    cp16(ldst + A_TILE_BYTES + sA_off + t * 2048,
                         lgb + (size_t)t * (16 * ROWB));
                }
            }
#pragma unroll
            for (int m2 = 0; m2 < 4; m2++)
#pragma unroll
                for (int n2 = 0; n2 < 4; n2++) {
                    mma16816(acc[m2][n2 * 2],     af[m2], bf[n2][0], bf[n2][1]);
                    mma16816(acc[m2][n2 * 2 + 1], af[m2], bf[n2][2], bf[n2][3]);
                }
        }
        if (doload) {
            CP_MBAR_ARRIVE(mb + ec_s * 16);    // full[ec_s] when this thread's cps land
            if (++ec_s == STAGES) { ec_s = 0; ec_p ^= 1; }
        }
        if (++fc_s == STAGES) { fc_s = 0; fc_p ^= 1; }
    }

    // ---- epilogue: accum regs -> gmem ----
    int r0o = mt * BM + wm * 64;
    int c0o = ntb * BN + wn * 64;
#pragma unroll
    for (int m2 = 0; m2 < 4; m2++)
#pragma unroll
        for (int rr = 0; rr < 2; rr++) {
            int row = r0o + m2 * 16 + rr * 8 + (lane >> 2);
            float* orow = out + (size_t)row * ODIM + c0o + (lane & 3) * 2;
#pragma unroll
            for (int n8 = 0; n8 < 8; n8++) {
                float2 v = make_float2(acc[m2][n8][rr * 2], acc[m2][n8][rr * 2 + 1]);
                *(float2*)(orow + n8 * 8) = v;
            }
        }
}

// ---------------- host launch ----------------
extern "C" void kernel_launch(void* const* d_in, const int* in_sizes, int n_in,
                              void* d_out, int out_size) {
    const float* x            = (const float*)d_in[0];
    const float* scale_base   = (const float*)d_in[1];
    const float* scale_spline = (const float*)d_in[2];
    const float* coeff        = (const float*)d_in[3];
    float* out = (float*)d_out;

    cudaFuncSetAttribute(kan_gemm, cudaFuncAttributeMaxDynamicSharedMemorySize, SMEM_BYTES);

    kan_features<<<(BATCH * IDIM) / 256, 256>>>(x);
    kan_pack<<<(ODIM * IDIM) / 256, 256>>>(scale_base, scale_spline, coeff);
    kan_gemm<<<(BATCH / BM) * (ODIM / BN), NTH, SMEM_BYTES>>>(out);
}

// round 12
// speedup vs baseline: 1.1212x; 1.1212x over previous
#include <cuda_runtime.h>
#include <cuda_bf16.h>
#include <stdint.h>
#include <math.h>

// ---------------- problem constants ----------------
#define GSIZE   8
#define IDIM    1024
#define ODIM    1024
#define BATCH   4096
#define NF      19                  // 8 cos + 8 sin + 3 base-split features
#define KDIM    (NF * IDIM)         // 19456

// ---------------- GEMM tiling ----------------
#define BM      128
#define BN      128
#define BK      64                  // K per pipeline stage (128B rows)
#define NKC     (KDIM / BK)         // 304 total chunks
#define KSPLIT  4
#define NKCS    (NKC / KSPLIT)      // 76 chunks per split job
#define STAGES  3
#define NTH     128                 // 4 warps: 2 (m) x 2 (n), warp tile 64x64

#define A_TILE_BYTES (BM * BK * 2)            // 16384
#define B_TILE_BYTES (BN * BK * 2)            // 16384
#define STAGE_BYTES  (A_TILE_BYTES + B_TILE_BYTES) // 32768
#define SMEM_BYTES   (1024 + STAGES * STAGE_BYTES) // 99328 -> 2 CTAs/SM

#define ROWB         (KDIM * 2)     // gmem row stride in bytes (38912, 16B-aligned)

// ---------------- scratch (no allocs allowed) ----------------
__device__ __align__(1024) __nv_bfloat16 g_A[(size_t)BATCH * KDIM]; // ~152 MB
__device__ __align__(1024) __nv_bfloat16 g_W[(size_t)ODIM  * KDIM]; // ~40 MB

// ---------------- PTX helpers (base-arch only: sm_80-level) ----------------
__device__ __forceinline__ uint32_t smem_u32(const void* p) {
    uint32_t a;
    asm("{ .reg .u64 t; cvta.to.shared.u64 t, %1; cvt.u32.u64 %0, t; }" : "=r"(a) : "l"(p));
    return a;
}

__device__ __forceinline__ void cp16(uint32_t s, const void* g) {
    asm volatile("cp.async.cg.shared.global [%0], [%1], 16;" :: "r"(s), "l"(g) : "memory");
}
#define CP_COMMIT() asm volatile("cp.async.commit_group;" ::: "memory")
#define CP_WAIT(n)  asm volatile("cp.async.wait_group %0;" :: "n"(n) : "memory")

__device__ __forceinline__ void ldsm_x4(uint32_t* r, uint32_t addr) {
    asm volatile("ldmatrix.sync.aligned.m8n8.x4.shared.b16 {%0,%1,%2,%3}, [%4];"
                 : "=r"(r[0]), "=r"(r[1]), "=r"(r[2]), "=r"(r[3]) : "r"(addr));
}

__device__ __forceinline__ void mma16816(float* d, const uint32_t* a, uint32_t b0, uint32_t b1) {
    asm volatile("mma.sync.aligned.m16n8k16.row.col.f32.bf16.bf16.f32 "
                 "{%0,%1,%2,%3}, {%4,%5,%6,%7}, {%8,%9}, {%0,%1,%2,%3};"
                 : "+f"(d[0]), "+f"(d[1]), "+f"(d[2]), "+f"(d[3])
                 : "r"(a[0]), "r"(a[1]), "r"(a[2]), "r"(a[3]), "r"(b0), "r"(b1));
}

// ---------------- kernel 0: zero the output (atomicAdd target) ----------------
__global__ void __launch_bounds__(256) kan_zero(float4* __restrict__ out4) {
    out4[blockIdx.x * 256 + threadIdx.x] = make_float4(0.f, 0.f, 0.f, 0.f);
}

// ---------------- kernel 1: feature matrix F[b, k] ----------------
// k = t*IDIM + i; t: 0..7 cos((t+1)x), 8..15 sin((t-7)x), 16 silu_hi, 17 silu_lo, 18 silu_hi
__global__ void __launch_bounds__(256) kan_features(const float* __restrict__ x) {
    int idx = blockIdx.x * blockDim.x + threadIdx.x;     // b*IDIM + i
    if (idx >= BATCH * IDIM) return;
    int b = idx >> 10, i = idx & (IDIM - 1);
    float v = x[idx];

    float s1, c1;
    __sincosf(v, &s1, &c1);     // |err| ~1e-6 over N(0,1) range; bf16 eps dominates
    __nv_bfloat16* dst = g_A + (size_t)b * KDIM + i;

    float ck = c1, sk = s1;
    dst[0 * IDIM] = __float2bfloat16_rn(ck);
    dst[8 * IDIM] = __float2bfloat16_rn(sk);
#pragma unroll
    for (int g = 1; g < GSIZE; g++) {
        float cn = ck * c1 - sk * s1;   // exact angle-addition recurrence
        float sn = sk * c1 + ck * s1;
        ck = cn; sk = sn;
        dst[g * IDIM]       = __float2bfloat16_rn(ck);
        dst[(8 + g) * IDIM] = __float2bfloat16_rn(sk);
    }

    float sig = 1.0f / (1.0f + __expf(-v));
    float su  = v * sig;                             // silu(x)
    __nv_bfloat16 hi = __float2bfloat16_rn(su);
    float lo = su - __bfloat162float(hi);
    dst[16 * IDIM] = hi;
    dst[17 * IDIM] = __float2bfloat16_rn(lo);
    dst[18 * IDIM] = hi;
}

// ---------------- kernel 2: packed weights W[o, k] ----------------
__global__ void __launch_bounds__(256) kan_pack(const float* __restrict__ scale_base,
                                                const float* __restrict__ scale_spline,
                                                const float* __restrict__ coeff) {
    int idx = blockIdx.x * blockDim.x + threadIdx.x;     // o*IDIM + i
    if (idx >= ODIM * IDIM) return;
    int o = idx >> 10, i = idx & (IDIM - 1);

    float ss = scale_spline[idx];
    __nv_bfloat16* dst = g_W + (size_t)o * KDIM + i;
    const float* c0 = coeff + ((size_t)o * IDIM + i) * GSIZE;
    const float* c1 = coeff + (size_t)ODIM * IDIM * GSIZE + ((size_t)o * IDIM + i) * GSIZE;

#pragma unroll
    for (int g = 0; g < GSIZE; g++) {
        dst[g * IDIM]       = __float2bfloat16_rn(ss * c0[g]);   // pairs with cos
        dst[(8 + g) * IDIM] = __float2bfloat16_rn(ss * c1[g]);   // pairs with sin
    }
    float sb = scale_base[idx];
    __nv_bfloat16 bh = __float2bfloat16_rn(sb);
    float bl = sb - __bfloat162float(bh);
    dst[16 * IDIM] = bh;                         // pairs with silu_hi
    dst[17 * IDIM] = bh;                         // pairs with silu_lo
    dst[18 * IDIM] = __float2bfloat16_rn(bl);    // pairs with silu_hi
}

// ---------------- kernel 3: pipelined HMMA GEMM out += F @ W^T (split-K x4) ----------------
// 1024 CTAs (32 m x 8 n x 4 k-splits), 2 CTAs/SM, 128 threads (4 warps of 64x64),
// 3-stage cp.async pipeline; partials accumulated via RED (atomicAdd, no return).

__global__ void __launch_bounds__(NTH, 2)
kan_gemm(float* __restrict__ out) {
    extern __shared__ char smem_raw[];
    uint32_t sbase = (smem_u32(smem_raw) + 1023u) & ~1023u;

    int tid  = threadIdx.x;
    int lane = tid & 31, wid = tid >> 5;
    int wm = wid & 1, wn = wid >> 1;           // 2 x 2 warp grid, warp tile 64x64
    int mt  = blockIdx.x & 31;                 // 32 m-tiles
    int ntb = (blockIdx.x >> 5) & 7;           // 8  n-tiles
    int ksp = blockIdx.x >> 8;                 // 4  k-splits
    int kbase = ksp * NKCS;                    // this job's first chunk
    int off = ((blockIdx.x / 148) & 1) ? (NKCS / 2) : 0;  // stagger co-residents

    const char* gA0 = (const char*)(g_A + (size_t)(mt * BM) * KDIM);
    const char* gB0 = (const char*)(g_W + (size_t)(ntb * BN) * KDIM);

    // per-thread stage-load addressing (row0 = tid/8 in 0..15, +16 per sub-load)
    int r0   = tid >> 3;
    int colb = (tid & 7) * 16;
    uint32_t swc    = (uint32_t)(colb ^ ((r0 & 7) * 16));   // swizzle invariant in t
    uint32_t sA_off = (uint32_t)r0 * 128 + swc;
    size_t   g_off  = (size_t)r0 * ROWB + colb;

    // ---- prologue: fill STAGES-1 stages ----
#pragma unroll
    for (int s = 0; s < STAGES - 1; s++) {
        int c = s + off; if (c >= NKCS) c -= NKCS;
        c += kbase;
        uint32_t st = sbase + s * STAGE_BYTES;
        const char* ga = gA0 + (size_t)c * 128 + g_off;
        const char* gb = gB0 + (size_t)c * 128 + g_off;
#pragma unroll
        for (int t = 0; t < 8; t++) {
            cp16(st + sA_off + t * 2048,                ga + (size_t)t * (16 * ROWB));
            cp16(st + A_TILE_BYTES + sA_off + t * 2048, gb + (size_t)t * (16 * ROWB));
        }
        CP_COMMIT();
    }

    float acc[4][8][4];                        // [m16 tile][n8 tile][frag] = 128 regs
#pragma unroll
    for (int a = 0; a < 4; a++)
#pragma unroll
        for (int b = 0; b < 8; b++)
#pragma unroll
            for (int c = 0; c < 4; c++) acc[a][b][c] = 0.f;

    // per-lane ldmatrix address components
    int laA = lane & 15;                       // A row offset within m16
    int lcA = (lane >> 4) * 16;                // A col byte offset (k8 half)
    int bjj = lane >> 3;                       // B quad index
    int laB = ((bjj >> 1) << 3) + (lane & 7);  // B row offset within n16
    int lcB = (bjj & 1) * 16;                  // B col byte offset

    int sc = 0;                                // compute stage
    int sl = STAGES - 1;                       // load stage
    for (int kc = 0; kc < NKCS; kc++) {
        CP_WAIT(STAGES - 2);
        __syncthreads();

        int  lkc    = kc + STAGES - 1;
        bool doload = lkc < NKCS;
        int  lck    = lkc + off; if (lck >= NKCS) lck -= NKCS;
        lck += kbase;
        uint32_t ldst = sbase + sl * STAGE_BYTES;
        const char* lga = gA0 + (size_t)lck * 128 + g_off;
        const char* lgb = gB0 + (size_t)lck * 128 + g_off;

        uint32_t sA = sbase + sc * STAGE_BYTES;
        uint32_t sB = sA + A_TILE_BYTES;

#pragma unroll
        for (int ks = 0; ks < 4; ks++) {       // 4 x k16 per stage
            uint32_t af[4][4];
#pragma unroll
            for (int m2 = 0; m2 < 4; m2++) {
                int row = wm * 64 + m2 * 16 + laA;
                uint32_t addr = sA + row * 128 + ((ks * 32 + lcA) ^ ((row & 7) * 16));
                ldsm_x4(af[m2], addr);
            }
            uint32_t bf[4][4];
#pragma unroll
            for (int n2 = 0; n2 < 4; n2++) {
                int row = wn * 64 + n2 * 16 + laB;
                uint32_t addr = sB + row * 128 + ((ks * 32 + lcB) ^ ((row & 7) * 16));
                ldsm_x4(bf[n2], addr);         // r0,r1: n0-7 (k0,k8); r2,r3: n8-15
            }
            // spread next-stage loads under the MMA block (4 of 16 per ks group)
            if (doload) {
#pragma unroll
                for (int u = 0; u < 2; u++) {
                    int t = ks * 2 + u;
                    cp16(ldst + sA_off + t * 2048,
                         lga + (size_t)t * (16 * ROWB));
                    cp16(ldst + A_TILE_BYTES + sA_off + t * 2048,
                         lgb + (size_t)t * (16 * ROWB));
                }
            }
#pragma unroll
            for (int m2 = 0; m2 < 4; m2++)
#pragma unroll
                for (int n2 = 0; n2 < 4; n2++) {
                    mma16816(acc[m2][n2 * 2],     af[m2], bf[n2][0], bf[n2][1]);
                    mma16816(acc[m2][n2 * 2 + 1], af[m2], bf[n2][2], bf[n2][3]);
                }
        }
        CP_COMMIT();
        sl = (sl + 1 == STAGES) ? 0 : sl + 1;
        sc = (sc + 1 == STAGES) ? 0 : sc + 1;
    }

    // ---- epilogue: RED partials into out ----
    int r0o = mt * BM + wm * 64;
    int c0o = ntb * BN + wn * 64;
#pragma unroll
    for (int m2 = 0; m2 < 4; m2++)
#pragma unroll
        for (int rr = 0; rr < 2; rr++) {
            int row = r0o + m2 * 16 + rr * 8 + (lane >> 2);
            float* orow = out + (size_t)row * ODIM + c0o + (lane & 3) * 2;
#pragma unroll
            for (int n8 = 0; n8 < 8; n8++) {
                atomicAdd(orow + n8 * 8,     acc[m2][n8][rr * 2]);
                atomicAdd(orow + n8 * 8 + 1, acc[m2][n8][rr * 2 + 1]);
            }
        }
}

// ---------------- host launch ----------------
extern "C" void kernel_launch(void* const* d_in, const int* in_sizes, int n_in,
                              void* d_out, int out_size) {
    const float* x            = (const float*)d_in[0];
    const float* scale_base   = (const float*)d_in[1];
    const float* scale_spline = (const float*)d_in[2];
    const float* coeff        = (const float*)d_in[3];
    float* out = (float*)d_out;

    cudaFuncSetAttribute(kan_gemm, cudaFuncAttributeMaxDynamicSharedMemorySize, SMEM_BYTES);

    kan_zero<<<(BATCH * ODIM / 4) / 256, 256>>>((float4*)out);
    kan_features<<<(BATCH * IDIM) / 256, 256>>>(x);
    kan_pack<<<(ODIM * IDIM) / 256, 256>>>(scale_base, scale_spline, coeff);
    kan_gemm<<<(BATCH / BM) * (ODIM / BN) * KSPLIT, NTH, SMEM_BYTES>>>(out);
}